// round 2
// baseline (speedup 1.0000x reference)
#include <cuda_runtime.h>
#include <cstdint>
#include <math.h>

// ---------------------------------------------------------------------------
// SoftEmbRescore: out[i,j] = (x @ G)[i,j] / max(s_i * e_j, 1e-8)
//   G   = emb @ emb^T                  (1024 x 1024, built once per launch)
//   e_j = sqrt(G[j,j])                 (= ||emb_j||)
//   s_i = sqrt( sum_j dots[i,j] * x[i,j] )   (= ||x_i @ emb||, via x G x^T)
// Single 65536x1024x1024 TF32 GEMM instead of the reference's two fp32 GEMMs.
// ---------------------------------------------------------------------------

namespace {
constexpr int MDIM = 65536;
constexpr int NDIM = 1024;
constexpr int KDIM = 1024;

constexpr int BM = 128;
constexpr int BN = 128;
constexpr int BK = 16;
constexpr int LDSS = BK + 4;                  // 20-float stride: conflict-free frag reads
constexpr int NTHREADS = 256;
constexpr int NT = KDIM / BK;                 // 64 k-tiles
constexpr int STAGE_FLOATS = (BM + BN) * LDSS;  // 5120
constexpr int NCTA_N = NDIM / BN;             // 8
}

__device__ __align__(16) float g_mat[(size_t)NDIM * NDIM];   // 4 MB scratch
__device__ __align__(16) float e_norm[NDIM];
__device__ __align__(16) float s2_part[NCTA_N][MDIM];        // deterministic partials
__device__ __align__(16) float s_row[MDIM];

__device__ __forceinline__ uint32_t f2tf32(float f) {
    uint32_t r;
    asm("cvt.rna.tf32.f32 %0, %1;" : "=r"(r) : "f"(f));
    return r;
}

__device__ __forceinline__ void mma_tf32(float* d, const uint32_t* a, const uint32_t* b) {
    asm volatile(
        "mma.sync.aligned.m16n8k8.row.col.f32.tf32.tf32.f32 "
        "{%0,%1,%2,%3}, {%4,%5,%6,%7}, {%8,%9}, {%0,%1,%2,%3};"
        : "+f"(d[0]), "+f"(d[1]), "+f"(d[2]), "+f"(d[3])
        : "r"(a[0]), "r"(a[1]), "r"(a[2]), "r"(a[3]), "r"(b[0]), "r"(b[1]));
}

#define CP_ASYNC16(dst, src) \
    asm volatile("cp.async.cg.shared.global [%0], [%1], 16;" :: "r"(dst), "l"(src))
#define CP_COMMIT() asm volatile("cp.async.commit_group;")
#define CP_WAIT1()  asm volatile("cp.async.wait_group 1;")
#define CP_WAIT0()  asm volatile("cp.async.wait_group 0;")

// MODE 0: G = emb @ emb^T, store tf32-rounded into g_mat.
// MODE 1: dots = x @ G -> C (raw), plus per-CTA row s^2 partials from dots*x.
template <int MODE>
__global__ __launch_bounds__(NTHREADS, 2)
void gemm_tf32_kernel(const float* __restrict__ A, const float* __restrict__ Bin,
                      float* __restrict__ C)
{
    // 16-byte alignment is REQUIRED: cp.async.cg ...,16 traps on misaligned
    // shared destinations, and the base of a plain __shared__ float array is
    // only guaranteed 4-byte aligned.
    __shared__ __align__(16) float smem[2 * STAGE_FLOATS + 2 * BM];
    const float* B = (MODE == 1) ? g_mat : Bin;   // B is [N,K] K-contig (G symmetric)

    const int tid = threadIdx.x;
    const int m0 = blockIdx.y * BM;
    const int n0 = blockIdx.x * BN;

    auto load_stage = [&](int s, int kt) {
        const float* Ag = A + (size_t)m0 * KDIM + kt * BK;
        const float* Bg = B + (size_t)n0 * KDIM + kt * BK;
        float* Asm = smem + s * STAGE_FLOATS;
        float* Bsm = Asm + BM * LDSS;
        #pragma unroll
        for (int i = 0; i < 2; ++i) {
            int chunk = tid + i * NTHREADS;        // 512 float4 per matrix
            int r = chunk >> 2;                    // row 0..127
            int c = (chunk & 3) * 4;               // col 0,4,8,12
            CP_ASYNC16((uint32_t)__cvta_generic_to_shared(Asm + r * LDSS + c),
                       Ag + (size_t)r * KDIM + c);
            CP_ASYNC16((uint32_t)__cvta_generic_to_shared(Bsm + r * LDSS + c),
                       Bg + (size_t)r * KDIM + c);
        }
        CP_COMMIT();
    };

    const int warp = tid >> 5;
    const int lane = tid & 31;
    const int wm = warp & 3;      // 4 warps along M
    const int wn = warp >> 2;     // 2 warps along N
    const int mb = wm * 32;
    const int nb = wn * 64;
    const int grp = lane >> 2;    // 0..7
    const int tig = lane & 3;     // 0..3

    float d[2][8][4];
    #pragma unroll
    for (int mi = 0; mi < 2; ++mi)
        #pragma unroll
        for (int ni = 0; ni < 8; ++ni)
            #pragma unroll
            for (int r = 0; r < 4; ++r) d[mi][ni][r] = 0.f;

    load_stage(0, 0);

    for (int t = 0; t < NT; ++t) {
        if (t + 1 < NT) {
            load_stage((t + 1) & 1, t + 1);
            CP_WAIT1();
        } else {
            CP_WAIT0();
        }
        __syncthreads();

        const float* Asm = smem + (t & 1) * STAGE_FLOATS;
        const float* Bsm = Asm + BM * LDSS;

        #pragma unroll
        for (int kk = 0; kk < BK; kk += 8) {
            uint32_t a[2][4];
            #pragma unroll
            for (int mi = 0; mi < 2; ++mi) {
                const float* p = Asm + (mb + mi * 16 + grp) * LDSS + kk + tig;
                a[mi][0] = f2tf32(p[0]);
                a[mi][1] = f2tf32(p[8 * LDSS]);
                a[mi][2] = f2tf32(p[4]);
                a[mi][3] = f2tf32(p[8 * LDSS + 4]);
            }
            uint32_t b[8][2];
            #pragma unroll
            for (int ni = 0; ni < 8; ++ni) {
                const float* p = Bsm + (nb + ni * 8 + grp) * LDSS + kk + tig;
                if (MODE == 0) {
                    b[ni][0] = f2tf32(p[0]);
                    b[ni][1] = f2tf32(p[4]);
                } else {
                    b[ni][0] = __float_as_uint(p[0]);   // g_mat pre-rounded
                    b[ni][1] = __float_as_uint(p[4]);
                }
            }
            #pragma unroll
            for (int mi = 0; mi < 2; ++mi)
                #pragma unroll
                for (int ni = 0; ni < 8; ++ni)
                    mma_tf32(d[mi][ni], a[mi], b[ni]);
        }
        __syncthreads();
    }

    if (MODE == 0) {
        // Store G pre-rounded to tf32 so the main GEMM skips B-fragment cvt.
        #pragma unroll
        for (int mi = 0; mi < 2; ++mi) {
            #pragma unroll
            for (int ni = 0; ni < 8; ++ni) {
                int row = m0 + mb + mi * 16 + grp;
                int col = n0 + nb + ni * 8 + 2 * tig;
                g_mat[(size_t)row * NDIM + col]           = __uint_as_float(f2tf32(d[mi][ni][0]));
                g_mat[(size_t)row * NDIM + col + 1]       = __uint_as_float(f2tf32(d[mi][ni][1]));
                g_mat[(size_t)(row + 8) * NDIM + col]     = __uint_as_float(f2tf32(d[mi][ni][2]));
                g_mat[(size_t)(row + 8) * NDIM + col + 1] = __uint_as_float(f2tf32(d[mi][ni][3]));
            }
        }
    } else {
        // Write raw dots + accumulate s^2 partials (deterministic, no atomics).
        float rs[4] = {0.f, 0.f, 0.f, 0.f};   // [mi*2 + half]
        #pragma unroll
        for (int mi = 0; mi < 2; ++mi) {
            #pragma unroll
            for (int ni = 0; ni < 8; ++ni) {
                int row = m0 + mb + mi * 16 + grp;
                int col = n0 + nb + ni * 8 + 2 * tig;
                float2 d01 = make_float2(d[mi][ni][0], d[mi][ni][1]);
                float2 d23 = make_float2(d[mi][ni][2], d[mi][ni][3]);
                *reinterpret_cast<float2*>(C + (size_t)row * NDIM + col)       = d01;
                *reinterpret_cast<float2*>(C + (size_t)(row + 8) * NDIM + col) = d23;
                float2 x01 = *reinterpret_cast<const float2*>(A + (size_t)row * NDIM + col);
                float2 x23 = *reinterpret_cast<const float2*>(A + (size_t)(row + 8) * NDIM + col);
                rs[mi * 2 + 0] += d01.x * x01.x + d01.y * x01.y;
                rs[mi * 2 + 1] += d23.x * x23.x + d23.y * x23.y;
            }
        }
        #pragma unroll
        for (int r = 0; r < 4; ++r) {
            rs[r] += __shfl_xor_sync(0xffffffffu, rs[r], 1);
            rs[r] += __shfl_xor_sync(0xffffffffu, rs[r], 2);
        }
        float* s2buf = smem + 2 * STAGE_FLOATS;   // [2][BM], one slice per n-warp
        if (tig == 0) {
            #pragma unroll
            for (int q = 0; q < 4; ++q) {
                int mi = q >> 1, half = q & 1;
                int ml = mb + mi * 16 + half * 8 + grp;
                s2buf[wn * BM + ml] = rs[q];
            }
        }
        __syncthreads();
        if (tid < BM) {
            s2_part[blockIdx.x][m0 + tid] = s2buf[tid] + s2buf[BM + tid];
        }
    }
}

__global__ void diag_norm_kernel() {
    int j = blockIdx.x * blockDim.x + threadIdx.x;
    if (j < NDIM) e_norm[j] = sqrtf(fmaxf(g_mat[(size_t)j * NDIM + j], 0.f));
}

__global__ void rowsum_kernel() {
    int m = blockIdx.x * blockDim.x + threadIdx.x;
    if (m < MDIM) {
        float v = 0.f;
        #pragma unroll
        for (int c = 0; c < NCTA_N; ++c) v += s2_part[c][m];
        s_row[m] = sqrtf(fmaxf(v, 0.f));
    }
}

__global__ void finalize_kernel(float* __restrict__ out) {
    int m = blockIdx.x;
    int t = threadIdx.x;                       // 256 threads -> 1024 cols
    float s = s_row[m];
    float4* rp = reinterpret_cast<float4*>(out + (size_t)m * NDIM);
    const float4* ep = reinterpret_cast<const float4*>(e_norm);
    float4 dv = rp[t];
    float4 ev = ep[t];
    dv.x = __fdividef(dv.x, fmaxf(s * ev.x, 1e-8f));
    dv.y = __fdividef(dv.y, fmaxf(s * ev.y, 1e-8f));
    dv.z = __fdividef(dv.z, fmaxf(s * ev.z, 1e-8f));
    dv.w = __fdividef(dv.w, fmaxf(s * ev.w, 1e-8f));
    rp[t] = dv;
}

extern "C" void kernel_launch(void* const* d_in, const int* in_sizes, int n_in,
                              void* d_out, int out_size) {
    const float* x   = (const float*)d_in[0];   // [1, 65536, 1024] fp32
    const float* emb = (const float*)d_in[1];   // [1024, 1024] fp32
    float* out = (float*)d_out;                 // [1, 65536, 1024] fp32
    (void)in_sizes; (void)n_in; (void)out_size;

    // 1) G = emb @ emb^T  (tf32 mma, tf32-rounded store)
    gemm_tf32_kernel<0><<<dim3(NDIM / BN, NDIM / BM), NTHREADS>>>(emb, emb, nullptr);
    // 2) e_j = sqrt(G[j,j])
    diag_norm_kernel<<<NDIM / 256, 256>>>();
    // 3) dots = x @ G -> out (raw), s^2 partials
    gemm_tf32_kernel<1><<<dim3(NDIM / BN, MDIM / BM), NTHREADS>>>(x, nullptr, out);
    // 4) s_i = sqrt(sum of partials)
    rowsum_kernel<<<MDIM / 256, 256>>>();
    // 5) out[i,j] = dots / max(s_i * e_j, 1e-8)   (in place)
    finalize_kernel<<<MDIM, 256>>>(out);
}